// round 5
// baseline (speedup 1.0000x reference)
#include <cuda_runtime.h>
#include <cstdint>

// ---------------- problem constants ----------------
#define BB    2048
#define TT    2
#define NTOK  49
#define NHEAD 16
#define HDIM  32
#define CDIM  512
#define NN2   (NTOK * NTOK)        // 2401

// ---------------- scratch (device globals; no allocs allowed) ----------------
__device__ float g_q   [(size_t)BB * NTOK * CDIM];              // (B*N, C)   Q * scale
__device__ float g_kv  [(size_t)BB * TT * NTOK * 2 * CDIM];     // (B*T*N, 2C) [k | v]
__device__ float g_attn[(size_t)BB * TT * NTOK * CDIM];         // (B*T*N, C)
__device__ float g_bias[NHEAD * NN2];                           // (H, N, N)

// ---------------- f32x2 packed-FMA helpers (Blackwell FFMA2) ----------------
__device__ __forceinline__ unsigned long long pack2(float a) {
    unsigned long long r;
    unsigned int ai = __float_as_uint(a);
    asm("mov.b64 %0, {%1, %1};" : "=l"(r) : "r"(ai));
    return r;
}
__device__ __forceinline__ void fma2(unsigned long long& c,
                                     unsigned long long a,
                                     unsigned long long b) {
    asm("fma.rn.f32x2 %0, %1, %2, %3;" : "=l"(c) : "l"(a), "l"(b), "l"(c));
}
__device__ __forceinline__ float2 unpack2(unsigned long long p) {
    unsigned int lo, hi;
    asm("mov.b64 {%0, %1}, %2;" : "=r"(lo), "=r"(hi) : "l"(p));
    return make_float2(__uint_as_float(lo), __uint_as_float(hi));
}

// ---------------- bias gather: g_bias[h][i][j] = rpb[rel[i][j]][h] ----------------
__global__ void bias_gather_kernel(const float* __restrict__ rpb,
                                   const int* __restrict__ rel) {
    int g = blockIdx.x * 256 + threadIdx.x;
    if (g >= NHEAD * NN2) return;
    int h = g / NN2;
    int p = g - h * NN2;
    g_bias[g] = rpb[rel[p] * NHEAD + h];
}

// ---------------- GEMM: C[M,N] = alpha * (A[M,K] @ W[N,K]^T + bias[N]) ----------------
// BM=BN=128, BK=16, 256 threads, 8x8 micro-tile per thread, f32x2 FMA.
// Requires: M%128==0, N%128==0, K%16==0 (true for all three calls).
#define BMT 128
#define BNT 128
#define BKT 16
#define ROWP 132   // padded smem row (floats), 16B-aligned sub-offsets

__global__ __launch_bounds__(256)
void gemm_bias_kernel(const float* __restrict__ A,
                      const float* __restrict__ W,
                      const float* __restrict__ bias,
                      float* __restrict__ C,
                      int M, int N, int K, float alpha) {
    __shared__ __align__(16) float As[2][BKT * ROWP];
    __shared__ __align__(16) float Bs[2][BKT * ROWP];

    const int tid = threadIdx.x;
    const int tx  = tid & 15;      // 0..15 -> N
    const int ty  = tid >> 4;      // 0..15 -> M
    const int tx4 = tx * 4;
    const int ty4 = ty * 4;

    const int n0 = blockIdx.x * BNT;
    const int m0 = blockIdx.y * BMT;

    // global-load mapping: 512 float4 per operand tile, 2 per thread
    const int lrow = tid >> 2;            // 0..63
    const int lc4  = (tid & 3) * 4;       // k offset 0,4,8,12

    const float* Abase = A + (size_t)m0 * K;
    const float* Wbase = W + (size_t)n0 * K;

    float4 ra0, ra1, rb0, rb1;
    // prefetch k-tile 0
    ra0 = *reinterpret_cast<const float4*>(Abase + (size_t)lrow        * K + lc4);
    ra1 = *reinterpret_cast<const float4*>(Abase + (size_t)(lrow + 64) * K + lc4);
    rb0 = *reinterpret_cast<const float4*>(Wbase + (size_t)lrow        * K + lc4);
    rb1 = *reinterpret_cast<const float4*>(Wbase + (size_t)(lrow + 64) * K + lc4);

    // store tile 0 (transposed: As[k][m], Bs[k][n])
    {
        float* as = As[0]; float* bs = Bs[0];
        as[(lc4 + 0) * ROWP + lrow] = ra0.x;
        as[(lc4 + 1) * ROWP + lrow] = ra0.y;
        as[(lc4 + 2) * ROWP + lrow] = ra0.z;
        as[(lc4 + 3) * ROWP + lrow] = ra0.w;
        as[(lc4 + 0) * ROWP + lrow + 64] = ra1.x;
        as[(lc4 + 1) * ROWP + lrow + 64] = ra1.y;
        as[(lc4 + 2) * ROWP + lrow + 64] = ra1.z;
        as[(lc4 + 3) * ROWP + lrow + 64] = ra1.w;
        bs[(lc4 + 0) * ROWP + lrow] = rb0.x;
        bs[(lc4 + 1) * ROWP + lrow] = rb0.y;
        bs[(lc4 + 2) * ROWP + lrow] = rb0.z;
        bs[(lc4 + 3) * ROWP + lrow] = rb0.w;
        bs[(lc4 + 0) * ROWP + lrow + 64] = rb1.x;
        bs[(lc4 + 1) * ROWP + lrow + 64] = rb1.y;
        bs[(lc4 + 2) * ROWP + lrow + 64] = rb1.z;
        bs[(lc4 + 3) * ROWP + lrow + 64] = rb1.w;
    }
    __syncthreads();

    unsigned long long acc[8][4];
#pragma unroll
    for (int i = 0; i < 8; i++)
#pragma unroll
        for (int j = 0; j < 4; j++) acc[i][j] = 0ull;

    const int nsteps = K / BKT;
    int cur = 0;
#pragma unroll 1
    for (int t = 0; t < nsteps; ++t) {
        const bool more = (t + 1 < nsteps);
        if (more) {
            const int k0 = (t + 1) * BKT;
            ra0 = *reinterpret_cast<const float4*>(Abase + (size_t)lrow        * K + k0 + lc4);
            ra1 = *reinterpret_cast<const float4*>(Abase + (size_t)(lrow + 64) * K + k0 + lc4);
            rb0 = *reinterpret_cast<const float4*>(Wbase + (size_t)lrow        * K + k0 + lc4);
            rb1 = *reinterpret_cast<const float4*>(Wbase + (size_t)(lrow + 64) * K + k0 + lc4);
        }

#pragma unroll
        for (int kt = 0; kt < BKT; kt++) {
            const float* asr = As[cur] + kt * ROWP;
            const float* bsr = Bs[cur] + kt * ROWP;
            float4 a0 = *reinterpret_cast<const float4*>(asr + ty4);
            float4 a1 = *reinterpret_cast<const float4*>(asr + 64 + ty4);
            ulonglong2 b0 = *reinterpret_cast<const ulonglong2*>(bsr + tx4);
            ulonglong2 b1 = *reinterpret_cast<const ulonglong2*>(bsr + 64 + tx4);
            float av[8] = {a0.x, a0.y, a0.z, a0.w, a1.x, a1.y, a1.z, a1.w};
#pragma unroll
            for (int i = 0; i < 8; i++) {
                unsigned long long aa = pack2(av[i]);
                fma2(acc[i][0], aa, b0.x);
                fma2(acc[i][1], aa, b0.y);
                fma2(acc[i][2], aa, b1.x);
                fma2(acc[i][3], aa, b1.y);
            }
        }

        if (more) {
            float* as = As[cur ^ 1]; float* bs = Bs[cur ^ 1];
            as[(lc4 + 0) * ROWP + lrow] = ra0.x;
            as[(lc4 + 1) * ROWP + lrow] = ra0.y;
            as[(lc4 + 2) * ROWP + lrow] = ra0.z;
            as[(lc4 + 3) * ROWP + lrow] = ra0.w;
            as[(lc4 + 0) * ROWP + lrow + 64] = ra1.x;
            as[(lc4 + 1) * ROWP + lrow + 64] = ra1.y;
            as[(lc4 + 2) * ROWP + lrow + 64] = ra1.z;
            as[(lc4 + 3) * ROWP + lrow + 64] = ra1.w;
            bs[(lc4 + 0) * ROWP + lrow] = rb0.x;
            bs[(lc4 + 1) * ROWP + lrow] = rb0.y;
            bs[(lc4 + 2) * ROWP + lrow] = rb0.z;
            bs[(lc4 + 3) * ROWP + lrow] = rb0.w;
            bs[(lc4 + 0) * ROWP + lrow + 64] = rb1.x;
            bs[(lc4 + 1) * ROWP + lrow + 64] = rb1.y;
            bs[(lc4 + 2) * ROWP + lrow + 64] = rb1.z;
            bs[(lc4 + 3) * ROWP + lrow + 64] = rb1.w;
        }
        __syncthreads();
        cur ^= 1;
    }

    // epilogue
    float4 bv0 = *reinterpret_cast<const float4*>(bias + n0 + tx4);
    float4 bv1 = *reinterpret_cast<const float4*>(bias + n0 + 64 + tx4);
#pragma unroll
    for (int i = 0; i < 8; i++) {
        int row = m0 + ((i < 4) ? (ty4 + i) : (64 + ty4 + i - 4));
        float2 c0 = unpack2(acc[i][0]);
        float2 c1 = unpack2(acc[i][1]);
        float2 c2 = unpack2(acc[i][2]);
        float2 c3 = unpack2(acc[i][3]);
        float4 o0 = make_float4(alpha * (c0.x + bv0.x), alpha * (c0.y + bv0.y),
                                alpha * (c1.x + bv0.z), alpha * (c1.y + bv0.w));
        float4 o1 = make_float4(alpha * (c2.x + bv1.x), alpha * (c2.y + bv1.y),
                                alpha * (c3.x + bv1.z), alpha * (c3.y + bv1.w));
        float* crow = C + (size_t)row * N + n0;
        *reinterpret_cast<float4*>(crow + tx4)      = o0;
        *reinterpret_cast<float4*>(crow + 64 + tx4) = o1;
    }
}

// ---------------- attention: one block per (b, t, h) ----------------
// S = (q*scale) k^T + bias[h]; softmax rows; O = S v; write (bt*N+n, h*32+d)
#define QPAD 33
#define SPAD 52

__global__ __launch_bounds__(128)
void attn_kernel() {
    const int bh = blockIdx.x;
    const int h  = bh & (NHEAD - 1);
    const int bt = bh >> 4;          // 0 .. B*T-1
    const int b  = bt >> 1;          // T = 2

    __shared__ float sq[NTOK * QPAD];
    __shared__ float sk[NTOK * QPAD];
    __shared__ float sv[NTOK * QPAD];
    __shared__ float sS[NTOK * SPAD];

    const int tid = threadIdx.x;

    // load q/k/v head slices
    for (int p = tid; p < NTOK * HDIM; p += 128) {
        int i = p >> 5;
        int d = p & 31;
        sq[i * QPAD + d] = g_q [(size_t)(b  * NTOK + i) * CDIM      + h * HDIM + d];
        const float* kvrow = g_kv + (size_t)(bt * NTOK + i) * (2 * CDIM) + h * HDIM + d;
        sk[i * QPAD + d] = kvrow[0];
        sv[i * QPAD + d] = kvrow[CDIM];
    }
    __syncthreads();

    // scores + bias
    const float* biasH = g_bias + h * NN2;
    for (int p = tid; p < NN2; p += 128) {
        int i = p / NTOK;
        int j = p - i * NTOK;
        float s = 0.f;
        const float* qi = sq + i * QPAD;
        const float* kj = sk + j * QPAD;
#pragma unroll
        for (int d = 0; d < HDIM; d++) s += qi[d] * kj[d];
        sS[i * SPAD + j] = s + biasH[p];
    }
    __syncthreads();

    // softmax: one warp per row
    const int warp = tid >> 5;
    const int lane = tid & 31;
    for (int i = warp; i < NTOK; i += 4) {
        float* row = sS + i * SPAD;
        float x0 = row[lane];                                    // lane < 32 <= 49 always valid
        bool  v1 = (lane + 32) < NTOK;
        float x1 = v1 ? row[lane + 32] : -3.402823466e38f;
        float m = fmaxf(x0, x1);
#pragma unroll
        for (int off = 16; off > 0; off >>= 1)
            m = fmaxf(m, __shfl_xor_sync(0xffffffffu, m, off));
        float e0 = __expf(x0 - m);
        float e1 = v1 ? __expf(x1 - m) : 0.f;
        float s = e0 + e1;
#pragma unroll
        for (int off = 16; off > 0; off >>= 1)
            s += __shfl_xor_sync(0xffffffffu, s, off);
        float inv = 1.0f / s;
        row[lane] = e0 * inv;
        if (v1) row[lane + 32] = e1 * inv;
    }
    __syncthreads();

    // O = S @ v ; write to g_attn
    for (int p = tid; p < NTOK * HDIM; p += 128) {
        int i = p >> 5;
        int d = p & 31;
        const float* Si = sS + i * SPAD;
        float o = 0.f;
#pragma unroll
        for (int m = 0; m < NTOK; m++) o += Si[m] * sv[m * QPAD + d];
        g_attn[(size_t)(bt * NTOK + i) * CDIM + h * HDIM + d] = o;
    }
}

// ---------------- launch ----------------
extern "C" void kernel_launch(void* const* d_in, const int* in_sizes, int n_in,
                              void* d_out, int out_size) {
    const float* x       = (const float*)d_in[0];
    const float* memory  = (const float*)d_in[1];
    const float* rpb     = (const float*)d_in[2];
    const float* q_w     = (const float*)d_in[3];
    const float* q_b     = (const float*)d_in[4];
    const float* kv_w    = (const float*)d_in[5];
    const float* kv_b    = (const float*)d_in[6];
    const float* proj_w  = (const float*)d_in[7];
    const float* proj_b  = (const float*)d_in[8];
    const int*   rel_idx = (const int*)d_in[9];
    float* out = (float*)d_out;

    float *pq, *pkv, *pattn;
    cudaGetSymbolAddress((void**)&pq,    g_q);
    cudaGetSymbolAddress((void**)&pkv,   g_kv);
    cudaGetSymbolAddress((void**)&pattn, g_attn);

    const float scale = 0.17677669529663687f;   // 32^-0.5

    // 1) relative-position bias gather
    bias_gather_kernel<<<(NHEAD * NN2 + 255) / 256, 256>>>(rpb, rel_idx);

    // 2) Q = scale * (x @ q_w^T + q_b)          M=100352, N=512, K=512
    {
        dim3 grid(CDIM / BNT, (BB * NTOK) / BMT);
        gemm_bias_kernel<<<grid, 256>>>(x, q_w, q_b, pq,
                                        BB * NTOK, CDIM, CDIM, scale);
    }
    // 3) KV = memory @ kv_w^T + kv_b            M=200704, N=1024, K=512
    {
        dim3 grid((2 * CDIM) / BNT, (BB * TT * NTOK) / BMT);
        gemm_bias_kernel<<<grid, 256>>>(memory, kv_w, kv_b, pkv,
                                        BB * TT * NTOK, 2 * CDIM, CDIM, 1.0f);
    }
    // 4) attention
    attn_kernel<<<BB * TT * NHEAD, 128>>>();

    // 5) out = attn @ proj_w^T + proj_b         M=200704, N=512, K=512
    {
        dim3 grid(CDIM / BNT, (BB * TT * NTOK) / BMT);
        gemm_bias_kernel<<<grid, 256>>>(pattn, proj_w, proj_b, out,
                                        BB * TT * NTOK, CDIM, CDIM, 1.0f);
    }
    (void)in_sizes; (void)n_in; (void)out_size;
}

// round 6
// speedup vs baseline: 1.0004x; 1.0004x over previous
#include <cuda_runtime.h>
#include <cstdint>

// ---------------- problem constants ----------------
#define BB    2048
#define TT    2
#define NTOK  49
#define NHEAD 16
#define HDIM  32
#define CDIM  512
#define NN2   (NTOK * NTOK)        // 2401

// ---------------- scratch (device globals; no allocs allowed) ----------------
__device__ float g_q   [(size_t)BB * NTOK * CDIM];              // (B*N, C)   Q * scale
__device__ float g_kv  [(size_t)BB * TT * NTOK * 2 * CDIM];     // (B*T*N, 2C) [k | v]
__device__ float g_attn[(size_t)BB * TT * NTOK * CDIM];         // (B*T*N, C)
__device__ float g_bias[NHEAD * NN2];                           // (H, N, N)

// ---------------- f32x2 packed-FMA helpers (Blackwell FFMA2) ----------------
__device__ __forceinline__ unsigned long long pack2(float a) {
    unsigned long long r;
    unsigned int ai = __float_as_uint(a);
    asm("mov.b64 %0, {%1, %1};" : "=l"(r) : "r"(ai));
    return r;
}
__device__ __forceinline__ void fma2(unsigned long long& c,
                                     unsigned long long a,
                                     unsigned long long b) {
    asm("fma.rn.f32x2 %0, %1, %2, %3;" : "=l"(c) : "l"(a), "l"(b), "l"(c));
}
__device__ __forceinline__ float2 unpack2(unsigned long long p) {
    unsigned int lo, hi;
    asm("mov.b64 {%0, %1}, %2;" : "=r"(lo), "=r"(hi) : "l"(p));
    return make_float2(__uint_as_float(lo), __uint_as_float(hi));
}

// ---------------- bias gather: g_bias[h][i][j] = rpb[rel[i][j]][h] ----------------
__global__ void bias_gather_kernel(const float* __restrict__ rpb,
                                   const int* __restrict__ rel) {
    int g = blockIdx.x * 256 + threadIdx.x;
    if (g >= NHEAD * NN2) return;
    int h = g / NN2;
    int p = g - h * NN2;
    g_bias[g] = rpb[rel[p] * NHEAD + h];
}

// ---------------- GEMM: C[M,N] = alpha * (A[M,K] @ W[N,K]^T + bias[N]) ----------------
// BM=BN=128, BK=16, 256 threads, 8x8 micro-tile per thread, f32x2 FMA.
// Requires: M%128==0, N%128==0, K%16==0 (true for all three calls).
#define BMT 128
#define BNT 128
#define BKT 16
#define ROWP 132   // padded smem row (floats), 16B-aligned sub-offsets

__global__ __launch_bounds__(256)
void gemm_bias_kernel(const float* __restrict__ A,
                      const float* __restrict__ W,
                      const float* __restrict__ bias,
                      float* __restrict__ C,
                      int M, int N, int K, float alpha) {
    __shared__ __align__(16) float As[2][BKT * ROWP];
    __shared__ __align__(16) float Bs[2][BKT * ROWP];

    const int tid = threadIdx.x;
    const int tx  = tid & 15;      // 0..15 -> N
    const int ty  = tid >> 4;      // 0..15 -> M
    const int tx4 = tx * 4;
    const int ty4 = ty * 4;

    const int n0 = blockIdx.x * BNT;
    const int m0 = blockIdx.y * BMT;

    // global-load mapping: 512 float4 per operand tile, 2 per thread
    const int lrow = tid >> 2;            // 0..63
    const int lc4  = (tid & 3) * 4;       // k offset 0,4,8,12

    const float* Abase = A + (size_t)m0 * K;
    const float* Wbase = W + (size_t)n0 * K;

    float4 ra0, ra1, rb0, rb1;
    // prefetch k-tile 0
    ra0 = *reinterpret_cast<const float4*>(Abase + (size_t)lrow        * K + lc4);
    ra1 = *reinterpret_cast<const float4*>(Abase + (size_t)(lrow + 64) * K + lc4);
    rb0 = *reinterpret_cast<const float4*>(Wbase + (size_t)lrow        * K + lc4);
    rb1 = *reinterpret_cast<const float4*>(Wbase + (size_t)(lrow + 64) * K + lc4);

    // store tile 0 (transposed: As[k][m], Bs[k][n])
    {
        float* as = As[0]; float* bs = Bs[0];
        as[(lc4 + 0) * ROWP + lrow] = ra0.x;
        as[(lc4 + 1) * ROWP + lrow] = ra0.y;
        as[(lc4 + 2) * ROWP + lrow] = ra0.z;
        as[(lc4 + 3) * ROWP + lrow] = ra0.w;
        as[(lc4 + 0) * ROWP + lrow + 64] = ra1.x;
        as[(lc4 + 1) * ROWP + lrow + 64] = ra1.y;
        as[(lc4 + 2) * ROWP + lrow + 64] = ra1.z;
        as[(lc4 + 3) * ROWP + lrow + 64] = ra1.w;
        bs[(lc4 + 0) * ROWP + lrow] = rb0.x;
        bs[(lc4 + 1) * ROWP + lrow] = rb0.y;
        bs[(lc4 + 2) * ROWP + lrow] = rb0.z;
        bs[(lc4 + 3) * ROWP + lrow] = rb0.w;
        bs[(lc4 + 0) * ROWP + lrow + 64] = rb1.x;
        bs[(lc4 + 1) * ROWP + lrow + 64] = rb1.y;
        bs[(lc4 + 2) * ROWP + lrow + 64] = rb1.z;
        bs[(lc4 + 3) * ROWP + lrow + 64] = rb1.w;
    }
    __syncthreads();

    unsigned long long acc[8][4];
#pragma unroll
    for (int i = 0; i < 8; i++)
#pragma unroll
        for (int j = 0; j < 4; j++) acc[i][j] = 0ull;

    const int nsteps = K / BKT;
    int cur = 0;
#pragma unroll 1
    for (int t = 0; t < nsteps; ++t) {
        const bool more = (t + 1 < nsteps);
        if (more) {
            const int k0 = (t + 1) * BKT;
            ra0 = *reinterpret_cast<const float4*>(Abase + (size_t)lrow        * K + k0 + lc4);
            ra1 = *reinterpret_cast<const float4*>(Abase + (size_t)(lrow + 64) * K + k0 + lc4);
            rb0 = *reinterpret_cast<const float4*>(Wbase + (size_t)lrow        * K + k0 + lc4);
            rb1 = *reinterpret_cast<const float4*>(Wbase + (size_t)(lrow + 64) * K + k0 + lc4);
        }

#pragma unroll
        for (int kt = 0; kt < BKT; kt++) {
            const float* asr = As[cur] + kt * ROWP;
            const float* bsr = Bs[cur] + kt * ROWP;
            float4 a0 = *reinterpret_cast<const float4*>(asr + ty4);
            float4 a1 = *reinterpret_cast<const float4*>(asr + 64 + ty4);
            ulonglong2 b0 = *reinterpret_cast<const ulonglong2*>(bsr + tx4);
            ulonglong2 b1 = *reinterpret_cast<const ulonglong2*>(bsr + 64 + tx4);
            float av[8] = {a0.x, a0.y, a0.z, a0.w, a1.x, a1.y, a1.z, a1.w};
#pragma unroll
            for (int i = 0; i < 8; i++) {
                unsigned long long aa = pack2(av[i]);
                fma2(acc[i][0], aa, b0.x);
                fma2(acc[i][1], aa, b0.y);
                fma2(acc[i][2], aa, b1.x);
                fma2(acc[i][3], aa, b1.y);
            }
        }

        if (more) {
            float* as = As[cur ^ 1]; float* bs = Bs[cur ^ 1];
            as[(lc4 + 0) * ROWP + lrow] = ra0.x;
            as[(lc4 + 1) * ROWP + lrow] = ra0.y;
            as[(lc4 + 2) * ROWP + lrow] = ra0.z;
            as[(lc4 + 3) * ROWP + lrow] = ra0.w;
            as[(lc4 + 0) * ROWP + lrow + 64] = ra1.x;
            as[(lc4 + 1) * ROWP + lrow + 64] = ra1.y;
            as[(lc4 + 2) * ROWP + lrow + 64] = ra1.z;
            as[(lc4 + 3) * ROWP + lrow + 64] = ra1.w;
            bs[(lc4 + 0) * ROWP + lrow] = rb0.x;
            bs[(lc4 + 1) * ROWP + lrow] = rb0.y;
            bs[(lc4 + 2) * ROWP + lrow] = rb0.z;
            bs[(lc4 + 3) * ROWP + lrow] = rb0.w;
            bs[(lc4 + 0) * ROWP + lrow + 64] = rb1.x;
            bs[(lc4 + 1) * ROWP + lrow + 64] = rb1.y;
            bs[(lc4 + 2) * ROWP + lrow + 64] = rb1.z;
            bs[(lc4 + 3) * ROWP + lrow + 64] = rb1.w;
        }
        __syncthreads();
        cur ^= 1;
    }

    // epilogue
    float4 bv0 = *reinterpret_cast<const float4*>(bias + n0 + tx4);
    float4 bv1 = *reinterpret_cast<const float4*>(bias + n0 + 64 + tx4);
#pragma unroll
    for (int i = 0; i < 8; i++) {
        int row = m0 + ((i < 4) ? (ty4 + i) : (64 + ty4 + i - 4));
        float2 c0 = unpack2(acc[i][0]);
        float2 c1 = unpack2(acc[i][1]);
        float2 c2 = unpack2(acc[i][2]);
        float2 c3 = unpack2(acc[i][3]);
        float4 o0 = make_float4(alpha * (c0.x + bv0.x), alpha * (c0.y + bv0.y),
                                alpha * (c1.x + bv0.z), alpha * (c1.y + bv0.w));
        float4 o1 = make_float4(alpha * (c2.x + bv1.x), alpha * (c2.y + bv1.y),
                                alpha * (c3.x + bv1.z), alpha * (c3.y + bv1.w));
        float* crow = C + (size_t)row * N + n0;
        *reinterpret_cast<float4*>(crow + tx4)      = o0;
        *reinterpret_cast<float4*>(crow + 64 + tx4) = o1;
    }
}

// ---------------- attention: one block per (b, t, h) ----------------
// S = (q*scale) k^T + bias[h]; softmax rows; O = S v; write (bt*N+n, h*32+d)
#define QPAD 33
#define SPAD 52

__global__ __launch_bounds__(128)
void attn_kernel() {
    const int bh = blockIdx.x;
    const int h  = bh & (NHEAD - 1);
    const int bt = bh >> 4;          // 0 .. B*T-1
    const int b  = bt >> 1;          // T = 2

    __shared__ float sq[NTOK * QPAD];
    __shared__ float sk[NTOK * QPAD];
    __shared__ float sv[NTOK * QPAD];
    __shared__ float sS[NTOK * SPAD];

    const int tid = threadIdx.x;

    // load q/k/v head slices
    for (int p = tid; p < NTOK * HDIM; p += 128) {
        int i = p >> 5;
        int d = p & 31;
        sq[i * QPAD + d] = g_q [(size_t)(b  * NTOK + i) * CDIM      + h * HDIM + d];
        const float* kvrow = g_kv + (size_t)(bt * NTOK + i) * (2 * CDIM) + h * HDIM + d;
        sk[i * QPAD + d] = kvrow[0];
        sv[i * QPAD + d] = kvrow[CDIM];
    }
    __syncthreads();

    // scores + bias
    const float* biasH = g_bias + h * NN2;
    for (int p = tid; p < NN2; p += 128) {
        int i = p / NTOK;
        int j = p - i * NTOK;
        float s = 0.f;
        const float* qi = sq + i * QPAD;
        const float* kj = sk + j * QPAD;
#pragma unroll
        for (int d = 0; d < HDIM; d++) s += qi[d] * kj[d];
        sS[i * SPAD + j] = s + biasH[p];
    }
    __syncthreads();

    // softmax: one warp per row
    const int warp = tid >> 5;
    const int lane = tid & 31;
    for (int i = warp; i < NTOK; i += 4) {
        float* row = sS + i * SPAD;
        float x0 = row[lane];                                    // lane < 32 <= 49 always valid
        bool  v1 = (lane + 32) < NTOK;
        float x1 = v1 ? row[lane + 32] : -3.402823466e38f;
        float m = fmaxf(x0, x1);
#pragma unroll
        for (int off = 16; off > 0; off >>= 1)
            m = fmaxf(m, __shfl_xor_sync(0xffffffffu, m, off));
        float e0 = __expf(x0 - m);
        float e1 = v1 ? __expf(x1 - m) : 0.f;
        float s = e0 + e1;
#pragma unroll
        for (int off = 16; off > 0; off >>= 1)
            s += __shfl_xor_sync(0xffffffffu, s, off);
        float inv = 1.0f / s;
        row[lane] = e0 * inv;
        if (v1) row[lane + 32] = e1 * inv;
    }
    __syncthreads();

    // O = S @ v ; write to g_attn
    for (int p = tid; p < NTOK * HDIM; p += 128) {
        int i = p >> 5;
        int d = p & 31;
        const float* Si = sS + i * SPAD;
        float o = 0.f;
#pragma unroll
        for (int m = 0; m < NTOK; m++) o += Si[m] * sv[m * QPAD + d];
        g_attn[(size_t)(bt * NTOK + i) * CDIM + h * HDIM + d] = o;
    }
}

// ---------------- launch ----------------
extern "C" void kernel_launch(void* const* d_in, const int* in_sizes, int n_in,
                              void* d_out, int out_size) {
    const float* x       = (const float*)d_in[0];
    const float* memory  = (const float*)d_in[1];
    const float* rpb     = (const float*)d_in[2];
    const float* q_w     = (const float*)d_in[3];
    const float* q_b     = (const float*)d_in[4];
    const float* kv_w    = (const float*)d_in[5];
    const float* kv_b    = (const float*)d_in[6];
    const float* proj_w  = (const float*)d_in[7];
    const float* proj_b  = (const float*)d_in[8];
    const int*   rel_idx = (const int*)d_in[9];
    float* out = (float*)d_out;

    float *pq, *pkv, *pattn;
    cudaGetSymbolAddress((void**)&pq,    g_q);
    cudaGetSymbolAddress((void**)&pkv,   g_kv);
    cudaGetSymbolAddress((void**)&pattn, g_attn);

    const float scale = 0.17677669529663687f;   // 32^-0.5

    // 1) relative-position bias gather
    bias_gather_kernel<<<(NHEAD * NN2 + 255) / 256, 256>>>(rpb, rel_idx);

    // 2) Q = scale * (x @ q_w^T + q_b)          M=100352, N=512, K=512
    {
        dim3 grid(CDIM / BNT, (BB * NTOK) / BMT);
        gemm_bias_kernel<<<grid, 256>>>(x, q_w, q_b, pq,
                                        BB * NTOK, CDIM, CDIM, scale);
    }
    // 3) KV = memory @ kv_w^T + kv_b            M=200704, N=1024, K=512
    {
        dim3 grid((2 * CDIM) / BNT, (BB * TT * NTOK) / BMT);
        gemm_bias_kernel<<<grid, 256>>>(memory, kv_w, kv_b, pkv,
                                        BB * TT * NTOK, 2 * CDIM, CDIM, 1.0f);
    }
    // 4) attention
    attn_kernel<<<BB * TT * NHEAD, 128>>>();

    // 5) out = attn @ proj_w^T + proj_b         M=200704, N=512, K=512
    {
        dim3 grid(CDIM / BNT, (BB * TT * NTOK) / BMT);
        gemm_bias_kernel<<<grid, 256>>>(pattn, proj_w, proj_b, out,
                                        BB * TT * NTOK, CDIM, CDIM, 1.0f);
    }
    (void)in_sizes; (void)n_in; (void)out_size;
}

// round 8
// speedup vs baseline: 1.2899x; 1.2894x over previous
#include <cuda_runtime.h>
#include <cuda_bf16.h>
#include <cstdint>

#define BB 2048
#define TT 2
#define NTOK 49
#define NHEAD 16
#define HDIM 32
#define CDIM 512
#define NN2 (NTOK*NTOK)

// ---------------- scratch (device globals; no allocs allowed) ----------------
__device__ unsigned short g_xh[(size_t)BB*NTOK*CDIM],    g_xl[(size_t)BB*NTOK*CDIM];
__device__ unsigned short g_mh[(size_t)BB*TT*NTOK*CDIM], g_ml[(size_t)BB*TT*NTOK*CDIM];
__device__ unsigned short g_oh[(size_t)BB*TT*NTOK*CDIM], g_ol[(size_t)BB*TT*NTOK*CDIM];
__device__ unsigned short g_qwh[CDIM*CDIM],    g_qwl[CDIM*CDIM];
__device__ unsigned short g_kvwh[2*CDIM*CDIM], g_kvwl[2*CDIM*CDIM];
__device__ unsigned short g_pwh[CDIM*CDIM],    g_pwl[CDIM*CDIM];
__device__ float g_q [(size_t)BB*NTOK*CDIM];
__device__ float g_kv[(size_t)BB*TT*NTOK*2*CDIM];
__device__ float g_bias[NHEAD*NN2];

// ---------------- PTX helpers (base-target only: cp.async/ldmatrix/mma) -------
__device__ __forceinline__ uint32_t smem_u32(const void* p){
    uint32_t a;
    asm("{ .reg .u64 t; cvta.to.shared.u64 t, %1; cvt.u32.u64 %0, t; }":"=r"(a):"l"(p));
    return a;
}
#define CP16(d,s)   asm volatile("cp.async.cg.shared.global [%0], [%1], 16;"::"r"((uint32_t)(d)),"l"(s):"memory")
#define CP_COMMIT() asm volatile("cp.async.commit_group;":::"memory")
#define CP_WAIT1()  asm volatile("cp.async.wait_group 1;":::"memory")
#define CP_WAIT0()  asm volatile("cp.async.wait_group 0;":::"memory")

__device__ __forceinline__ void ldsm4(uint32_t* r, uint32_t addr){
    asm volatile("ldmatrix.sync.aligned.m8n8.x4.shared.b16 {%0,%1,%2,%3}, [%4];"
        : "=r"(r[0]),"=r"(r[1]),"=r"(r[2]),"=r"(r[3]) : "r"(addr));
}
__device__ __forceinline__ void mma16816(float* d, const uint32_t* a, const uint32_t* b){
    asm volatile("mma.sync.aligned.m16n8k16.row.col.f32.bf16.bf16.f32 "
        "{%0,%1,%2,%3}, {%4,%5,%6,%7}, {%8,%9}, {%0,%1,%2,%3};"
        : "+f"(d[0]),"+f"(d[1]),"+f"(d[2]),"+f"(d[3])
        : "r"(a[0]),"r"(a[1]),"r"(a[2]),"r"(a[3]), "r"(b[0]),"r"(b[1]));
}

// ---------------- fp32 -> bf16 hi/lo split ----------------
__global__ void split_kernel(const float* __restrict__ in,
                             unsigned short* __restrict__ hi,
                             unsigned short* __restrict__ lo, long long n4){
    long long i = (long long)blockIdx.x*256 + threadIdx.x;
    if (i >= n4) return;
    float4 v = reinterpret_cast<const float4*>(in)[i];
    float vs[4] = {v.x, v.y, v.z, v.w};
    unsigned short hb[4], lb[4];
#pragma unroll
    for (int c = 0; c < 4; c++){
        __nv_bfloat16 h = __float2bfloat16_rn(vs[c]);
        float r = vs[c] - __bfloat162float(h);
        hb[c] = __bfloat16_as_ushort(h);
        lb[c] = __bfloat16_as_ushort(__float2bfloat16_rn(r));
    }
    uint2 H, L;
    H.x = hb[0] | ((uint32_t)hb[1] << 16);  H.y = hb[2] | ((uint32_t)hb[3] << 16);
    L.x = lb[0] | ((uint32_t)lb[1] << 16);  L.y = lb[2] | ((uint32_t)lb[3] << 16);
    reinterpret_cast<uint2*>(hi)[i] = H;
    reinterpret_cast<uint2*>(lo)[i] = L;
}

// ---------------- bias gather ----------------
__global__ void bias_gather_kernel(const float* __restrict__ rpb,
                                   const int* __restrict__ rel){
    int g = blockIdx.x*256 + threadIdx.x;
    if (g >= NHEAD*NN2) return;
    int h = g / NN2, p = g - h*NN2;
    g_bias[g] = rpb[rel[p]*NHEAD + h];
}

// ---------------- warp-MMA GEMM: C = alpha*(A@W^T + bias) ----------------
// 3-term compensated bf16 (K'=1536 = AhWh|AlWh|AhWl). Tile 128x128, BK=32,
// 8 warps (2M x 4N), each warp 64x32 via m16n8k16. cp.async double buffer.
// smem rows padded to 80B -> conflict-free ldmatrix, no swizzle.
#define KPB 40   // halves per padded smem row (80 bytes)

__global__ __launch_bounds__(256)
void gemm_mma(const unsigned short* __restrict__ Ah, const unsigned short* __restrict__ Al,
              const unsigned short* __restrict__ Wh, const unsigned short* __restrict__ Wl,
              const float* __restrict__ bias, float* __restrict__ C, int N, float alpha){
    __shared__ __align__(16) unsigned short As[2][128*KPB];
    __shared__ __align__(16) unsigned short Ws[2][128*KPB];

    const int tid = threadIdx.x, lane = tid & 31, wid = tid >> 5;
    const int wm = wid & 1, wn = wid >> 1;              // 2 x 4 warp grid
    const int m0 = blockIdx.y * 128, n0 = blockIdx.x * 128;

    const uint32_t abase[2] = {smem_u32(As[0]), smem_u32(As[1])};
    const uint32_t wbase[2] = {smem_u32(Ws[0]), smem_u32(Ws[1])};

    const unsigned short* AP[3] = {Ah, Al, Ah};
    const unsigned short* WP[3] = {Wh, Wh, Wl};

    auto load_chunk = [&](int t, int b){
        const unsigned short* Ap = AP[t >> 4];
        const unsigned short* Wp = WP[t >> 4];
        const int k0 = (t & 15) * 32;
#pragma unroll
        for (int j = 0; j < 2; j++){
            int s = tid*2 + j;
            int r = s >> 2, c = s & 3;                  // r: 0..127, c: 16B chunk
            uint32_t off = (uint32_t)(r*80 + c*16);
            CP16(abase[b] + off, Ap + (size_t)(m0+r)*CDIM + k0 + c*8);
            CP16(wbase[b] + off, Wp + (size_t)(n0+r)*CDIM + k0 + c*8);
        }
        CP_COMMIT();
    };

    // precomputed lane offsets (bytes) within a buffer
    uint32_t a_off[4], b_off[2];
#pragma unroll
    for (int mt = 0; mt < 4; mt++)
        a_off[mt] = (uint32_t)((wm*64 + mt*16 + (lane & 15))*80 + ((lane >> 4) & 1)*16);
    {
        int g = lane >> 3;                              // 0..3
#pragma unroll
        for (int q = 0; q < 2; q++)
            b_off[q] = (uint32_t)((wn*32 + (2*q + (g >> 1))*8 + (lane & 7))*80 + (g & 1)*16);
    }

    float acc[4][4][4];
#pragma unroll
    for (int i = 0; i < 4; i++)
#pragma unroll
        for (int j = 0; j < 4; j++)
#pragma unroll
            for (int k = 0; k < 4; k++) acc[i][j][k] = 0.f;

    load_chunk(0, 0);
    load_chunk(1, 1);

    for (int t = 0; t < 48; ++t){
        const int b = t & 1;
        if (t >= 46) CP_WAIT0(); else CP_WAIT1();
        __syncthreads();

#pragma unroll
        for (int s = 0; s < 2; s++){
            uint32_t af[4][4], bf[2][4];
#pragma unroll
            for (int mt = 0; mt < 4; mt++) ldsm4(af[mt], abase[b] + a_off[mt] + s*32);
#pragma unroll
            for (int q = 0; q < 2; q++)    ldsm4(bf[q],  wbase[b] + b_off[q] + s*32);
#pragma unroll
            for (int mt = 0; mt < 4; mt++){
                mma16816(acc[mt][0], af[mt], bf[0] + 0);
                mma16816(acc[mt][1], af[mt], bf[0] + 2);
                mma16816(acc[mt][2], af[mt], bf[1] + 0);
                mma16816(acc[mt][3], af[mt], bf[1] + 2);
            }
        }
        __syncthreads();
        if (t + 2 < 48) load_chunk(t + 2, b);
    }

    // epilogue: d0,d1 -> (row, col..col+1); d2,d3 -> (row+8, ..)
#pragma unroll
    for (int mt = 0; mt < 4; mt++){
#pragma unroll
        for (int nt = 0; nt < 4; nt++){
            int rg = m0 + wm*64 + mt*16 + (lane >> 2);
            int cg = n0 + wn*32 + nt*8 + 2*(lane & 3);
            float b0 = bias[cg], b1 = bias[cg + 1];
            float2 o0 = make_float2(alpha*(acc[mt][nt][0] + b0), alpha*(acc[mt][nt][1] + b1));
            float2 o1 = make_float2(alpha*(acc[mt][nt][2] + b0), alpha*(acc[mt][nt][3] + b1));
            *reinterpret_cast<float2*>(C + (size_t)rg*N + cg)       = o0;
            *reinterpret_cast<float2*>(C + (size_t)(rg + 8)*N + cg) = o1;
        }
    }
}

// ---------------- attention: 4x4 register-blocked, bf16-split output ----------
#define QP 36    // row stride (floats) for q/k/v, 52 rows
#define SP 56    // row stride (floats) for S, 52 rows

__global__ __launch_bounds__(128)
void attn_kernel(){
    const int bh = blockIdx.x;
    const int h  = bh & (NHEAD-1);
    const int bt = bh >> 4;
    const int b  = bt >> 1;
    __shared__ __align__(16) float sq[52*QP], sk[52*QP], sv[52*QP], sS[52*SP];
    const int tid = threadIdx.x;

    // load q/k/v head slices; zero-pad rows 49..51
    for (int p = tid; p < 52*HDIM; p += 128){
        int i = p >> 5, d = p & 31;
        float qv = 0.f, kv = 0.f, vv = 0.f;
        if (i < NTOK){
            qv = g_q[(size_t)(b*NTOK+i)*CDIM + h*HDIM + d];
            const float* kvr = g_kv + (size_t)(bt*NTOK+i)*(2*CDIM) + h*HDIM + d;
            kv = kvr[0];
            vv = kvr[CDIM];
        }
        sq[i*QP+d] = qv;
        sk[i*QP+d] = kv;
        sv[i*QP+d] = vv;
    }
    __syncthreads();

    // scores + bias, 4x4 tiles over 52x52 (13x13 = 169 tiles)
    const float* biasH = g_bias + h*NN2;
    for (int p = tid; p < 169; p += 128){
        int ti = p / 13, tj = p - ti*13;
        int i0 = ti*4, j0 = tj*4;
        float a[4][4] = {};
#pragma unroll
        for (int dd = 0; dd < 8; dd++){
            float4 qa[4], kb[4];
#pragma unroll
            for (int r = 0; r < 4; r++) qa[r] = *reinterpret_cast<const float4*>(&sq[(i0+r)*QP + dd*4]);
#pragma unroll
            for (int c = 0; c < 4; c++) kb[c] = *reinterpret_cast<const float4*>(&sk[(j0+c)*QP + dd*4]);
#pragma unroll
            for (int r = 0; r < 4; r++)
#pragma unroll
                for (int c = 0; c < 4; c++)
                    a[r][c] += qa[r].x*kb[c].x + qa[r].y*kb[c].y + qa[r].z*kb[c].z + qa[r].w*kb[c].w;
        }
#pragma unroll
        for (int r = 0; r < 4; r++)
#pragma unroll
            for (int c = 0; c < 4; c++){
                int i = i0 + r, j = j0 + c;
                float bv = (i < NTOK && j < NTOK) ? biasH[i*NTOK + j] : 0.f;
                sS[i*SP + j] = a[r][c] + bv;
            }
    }
    __syncthreads();

    // softmax: one warp per row
    const int warp = tid >> 5, lane = tid & 31;
    for (int i = warp; i < NTOK; i += 4){
        float* row = sS + i*SP;
        float x0 = row[lane];
        bool  v1 = (lane + 32) < NTOK;
        float x1 = v1 ? row[lane+32] : -3.402823466e38f;
        float m = fmaxf(x0, x1);
#pragma unroll
        for (int o = 16; o > 0; o >>= 1) m = fmaxf(m, __shfl_xor_sync(0xffffffffu, m, o));
        float e0 = __expf(x0 - m);
        float e1 = v1 ? __expf(x1 - m) : 0.f;
        float s = e0 + e1;
#pragma unroll
        for (int o = 16; o > 0; o >>= 1) s += __shfl_xor_sync(0xffffffffu, s, o);
        float inv = 1.0f / s;
        row[lane] = e0*inv;
        if (v1) row[lane+32] = e1*inv;
    }
    __syncthreads();

    // O = S @ v : 4x4 tiles over (i, d) = 13 x 8 = 104 tiles; bf16-split write
    for (int p = tid; p < 104; p += 128){
        int ti = p >> 3, td = p & 7;
        int i0 = ti*4, d0 = td*4;
        float a[4][4] = {};
        for (int m = 0; m < NTOK; m++){
            float4 vv = *reinterpret_cast<const float4*>(&sv[m*QP + d0]);
            float s0 = sS[(i0+0)*SP + m];
            float s1 = sS[(i0+1)*SP + m];
            float s2 = sS[(i0+2)*SP + m];
            float s3 = sS[(i0+3)*SP + m];
            a[0][0] += s0*vv.x; a[0][1] += s0*vv.y; a[0][2] += s0*vv.z; a[0][3] += s0*vv.w;
            a[1][0] += s1*vv.x; a[1][1] += s1*vv.y; a[1][2] += s1*vv.z; a[1][3] += s1*vv.w;
            a[2][0] += s2*vv.x; a[2][1] += s2*vv.y; a[2][2] += s2*vv.z; a[2][3] += s2*vv.w;
            a[3][0] += s3*vv.x; a[3][1] += s3*vv.y; a[3][2] += s3*vv.z; a[3][3] += s3*vv.w;
        }
#pragma unroll
        for (int r = 0; r < 4; r++){
            int i = i0 + r;
            if (i >= NTOK) break;
            size_t idx = (size_t)(bt*NTOK + i)*CDIM + h*HDIM + d0;
            unsigned short hb[4], lb[4];
#pragma unroll
            for (int c = 0; c < 4; c++){
                __nv_bfloat16 hh = __float2bfloat16_rn(a[r][c]);
                hb[c] = __bfloat16_as_ushort(hh);
                lb[c] = __bfloat16_as_ushort(__float2bfloat16_rn(a[r][c] - __bfloat162float(hh)));
            }
            uint2 H, L;
            H.x = hb[0] | ((uint32_t)hb[1] << 16);  H.y = hb[2] | ((uint32_t)hb[3] << 16);
            L.x = lb[0] | ((uint32_t)lb[1] << 16);  L.y = lb[2] | ((uint32_t)lb[3] << 16);
            *reinterpret_cast<uint2*>(&g_oh[idx]) = H;
            *reinterpret_cast<uint2*>(&g_ol[idx]) = L;
        }
    }
}

// ---------------- launch ----------------
extern "C" void kernel_launch(void* const* d_in, const int* in_sizes, int n_in,
                              void* d_out, int out_size){
    const float* x      = (const float*)d_in[0];
    const float* memory = (const float*)d_in[1];
    const float* rpb    = (const float*)d_in[2];
    const float* q_w    = (const float*)d_in[3];
    const float* q_b    = (const float*)d_in[4];
    const float* kv_w   = (const float*)d_in[5];
    const float* kv_b   = (const float*)d_in[6];
    const float* proj_w = (const float*)d_in[7];
    const float* proj_b = (const float*)d_in[8];
    const int*   rel    = (const int*)d_in[9];
    float* out = (float*)d_out;

    unsigned short *xh,*xl,*mh,*ml,*oh,*ol,*qwh,*qwl,*kvwh,*kvwl,*pwh,*pwl;
    float *pq,*pkv;
    cudaGetSymbolAddress((void**)&xh,g_xh);     cudaGetSymbolAddress((void**)&xl,g_xl);
    cudaGetSymbolAddress((void**)&mh,g_mh);     cudaGetSymbolAddress((void**)&ml,g_ml);
    cudaGetSymbolAddress((void**)&oh,g_oh);     cudaGetSymbolAddress((void**)&ol,g_ol);
    cudaGetSymbolAddress((void**)&qwh,g_qwh);   cudaGetSymbolAddress((void**)&qwl,g_qwl);
    cudaGetSymbolAddress((void**)&kvwh,g_kvwh); cudaGetSymbolAddress((void**)&kvwl,g_kvwl);
    cudaGetSymbolAddress((void**)&pwh,g_pwh);   cudaGetSymbolAddress((void**)&pwl,g_pwl);
    cudaGetSymbolAddress((void**)&pq,g_q);      cudaGetSymbolAddress((void**)&pkv,g_kv);

    const float scale = 0.17677669529663687f;  // 32^-0.5

    bias_gather_kernel<<<(NHEAD*NN2 + 255)/256, 256>>>(rpb, rel);

    {   // fp32 -> bf16 hi/lo splits
        long long n4x = (long long)BB*NTOK*CDIM/4;
        long long n4m = (long long)BB*TT*NTOK*CDIM/4;
        split_kernel<<<(unsigned)((n4x+255)/256),256>>>(x, xh, xl, n4x);
        split_kernel<<<(unsigned)((n4m+255)/256),256>>>(memory, mh, ml, n4m);
        split_kernel<<<(CDIM*CDIM/4+255)/256,256>>>(q_w, qwh, qwl, CDIM*CDIM/4);
        split_kernel<<<(2*CDIM*CDIM/4+255)/256,256>>>(kv_w, kvwh, kvwl, 2*CDIM*CDIM/4);
        split_kernel<<<(CDIM*CDIM/4+255)/256,256>>>(proj_w, pwh, pwl, CDIM*CDIM/4);
    }

    {   // Q = scale*(x @ q_w^T + q_b)       M=100352 N=512
        dim3 g(CDIM/128, BB*NTOK/128);
        gemm_mma<<<g, 256>>>(xh, xl, qwh, qwl, q_b, pq, CDIM, scale);
    }
    {   // KV = memory @ kv_w^T + kv_b      M=200704 N=1024
        dim3 g(2*CDIM/128, BB*TT*NTOK/128);
        gemm_mma<<<g, 256>>>(mh, ml, kvwh, kvwl, kv_b, pkv, 2*CDIM, 1.0f);
    }
    attn_kernel<<<BB*TT*NHEAD, 128>>>();
    {   // out = attn @ proj_w^T + proj_b   M=200704 N=512
        dim3 g(CDIM/128, BB*TT*NTOK/128);
        gemm_mma<<<g, 256>>>(oh, ol, pwh, pwl, proj_b, out, CDIM, 1.0f);
    }
    (void)in_sizes; (void)n_in; (void)out_size;
}